// round 2
// baseline (speedup 1.0000x reference)
#include <cuda_runtime.h>
#include <cuda_bf16.h>
#include <cstdint>

// Problem constants (reference: NUM_ENVS=1024, MEM_SIZE=200, FEAT=512)
#define NUM_ENVS 1024
#define MEM_SIZE 200
#define FEAT     512
#define NOVELTY_THRESHOLD 0.5f

#define MEM_ELEMS ((size_t)NUM_ENVS * MEM_SIZE * FEAT)  // 104,857,600 floats

// Fused copy + scatter-replace kernel.
// One block per memory row: grid.x = E*M, block = 128 threads, each moving one
// float4 (512 floats = 2KB per row). The block picks its source: the original
// memory row, or obs_features[e] when this row is the replacement slot for a
// novel observation. Row 0's thread 0 also emits the updated mem_mask counter
// into the tail of the output (reference's second return value).
__global__ void __launch_bounds__(128)
reachability_update_kernel(
    const float* __restrict__ memory,         // [E, M, D]
    const float* __restrict__ obs_features,   // [E, D]
    const float* __restrict__ similarities,   // [E]
    const int*   __restrict__ mem_mask,       // [E]
    const int*   __restrict__ rand_idx,       // [E]
    float*       __restrict__ out,            // [E*M*D (+ E tail)]
    int write_mask_tail)
{
    const int row = blockIdx.x;          // 0 .. E*M-1
    const int e   = row / MEM_SIZE;
    const int slot_of_row = row - e * MEM_SIZE;

    // Per-env scalars (broadcast; L2-resident)
    const float s    = __ldg(&similarities[e]);
    const int   m    = __ldg(&mem_mask[e]);
    const bool  add  = (s > NOVELTY_THRESHOLD);
    const bool  full = (m == MEM_SIZE);

    const int new_mask = m + ((!full && add) ? 1 : 0);

    if (slot_of_row == 0 && threadIdx.x == 0 && write_mask_tail) {
        out[MEM_ELEMS + (size_t)e] = (float)new_mask;
    }

    // Target slot: full envs replace rand_idx, non-full append at new_mask-1 (== m).
    // When !add, no row is replaced.
    int target = -1;
    if (add) target = full ? __ldg(&rand_idx[e]) : (new_mask - 1);

    const bool replace = (slot_of_row == target);

    const float4* __restrict__ src = replace
        ? reinterpret_cast<const float4*>(obs_features + (size_t)e * FEAT)
        : reinterpret_cast<const float4*>(memory + (size_t)row * FEAT);
    float4* __restrict__ dst =
        reinterpret_cast<float4*>(out + (size_t)row * FEAT);

    dst[threadIdx.x] = src[threadIdx.x];
}

extern "C" void kernel_launch(void* const* d_in, const int* in_sizes, int n_in,
                              void* d_out, int out_size)
{
    // Inputs per reference order:
    //   0: memory        float32 [E, M, D]
    //   1: obs_features  float32 [E, D]
    //   2: similarities  float32 [E]
    //   3: mem_mask      int32   [E]
    //   4: rand_idx      int32   [E]
    const float* memory       = (const float*)d_in[0];
    const float* obs_features = (const float*)d_in[1];
    const float* similarities = (const float*)d_in[2];
    const int*   mem_mask     = (const int*)d_in[3];
    const int*   rand_idx     = (const int*)d_in[4];
    float*       out          = (float*)d_out;

    const int write_mask_tail = ((size_t)out_size > MEM_ELEMS) ? 1 : 0;

    reachability_update_kernel<<<NUM_ENVS * MEM_SIZE, 128>>>(
        memory, obs_features, similarities, mem_mask, rand_idx, out,
        write_mask_tail);
}

// round 3
// speedup vs baseline: 1.0812x; 1.0812x over previous
#include <cuda_runtime.h>
#include <cuda_bf16.h>
#include <cstdint>

// Problem constants (reference: NUM_ENVS=1024, MEM_SIZE=200, FEAT=512)
#define NUM_ENVS 1024
#define MEM_SIZE 200
#define FEAT     512
#define NOVELTY_THRESHOLD 0.5f

#define MEM_ELEMS  ((size_t)NUM_ENVS * MEM_SIZE * FEAT)   // 104,857,600 floats
#define MEM_F4     (MEM_ELEMS / 4)                        // 13,107,200 float4
#define F4_PER_ROW (FEAT / 4)                             // 128
#define UNROLL     4
#define BLOCK      256
// MEM_F4 / (BLOCK*UNROLL) = 13,107,200 / 1024 = 12,800 (exact, no tail)
#define GRID       ((int)(MEM_F4 / (BLOCK * UNROLL)))

// Fused streaming copy + conditional row replacement + mask tail.
// Each thread moves 4 independent float4s (front-batched MLP=4). Source per
// element is either the original memory or obs_features[e] when the element's
// row is the replacement slot for a novel observation.
__global__ void __launch_bounds__(BLOCK)
reachability_update_kernel(
    const float4* __restrict__ mem4,          // [E*M*128] float4 view of memory
    const float4* __restrict__ obs4,          // [E*128]   float4 view of obs_features
    const float*  __restrict__ similarities,  // [E]
    const int*    __restrict__ mem_mask,      // [E]
    const int*    __restrict__ rand_idx,      // [E]
    float4*       __restrict__ out4,          // float4 view of output memory
    float*        __restrict__ out,           // scalar view (for mask tail)
    int write_mask_tail)
{
    const size_t base = (size_t)blockIdx.x * (BLOCK * UNROLL) + threadIdx.x;

    const float4* src[UNROLL];
    float4 v[UNROLL];

    // Phase 1: resolve all source pointers (scalar loads are warp-uniform L2
    // broadcasts; independent across the 4 elements).
#pragma unroll
    for (int j = 0; j < UNROLL; j++) {
        const size_t i    = base + (size_t)j * BLOCK;
        const int    row  = (int)(i >> 7);          // /128 float4 per row
        const int    e    = row / MEM_SIZE;         // const-div -> mul
        const int    slot = row - e * MEM_SIZE;

        const float s    = __ldg(&similarities[e]);
        const int   m    = __ldg(&mem_mask[e]);
        const bool  add  = (s > NOVELTY_THRESHOLD);
        const bool  full = (m == MEM_SIZE);
        const int   nm   = m + ((!full && add) ? 1 : 0);

        int target = -1;
        if (add) target = full ? __ldg(&rand_idx[e]) : (nm - 1);

        src[j] = (slot == target)
               ? (obs4 + (size_t)e * F4_PER_ROW + (i & (F4_PER_ROW - 1)))
               : (mem4 + i);
    }

    // Phase 2: batched independent loads (MLP=4 per thread).
#pragma unroll
    for (int j = 0; j < UNROLL; j++) v[j] = __ldg(src[j]);

    // Phase 3: stores.
#pragma unroll
    for (int j = 0; j < UNROLL; j++) out4[base + (size_t)j * BLOCK] = v[j];

    // Mask tail: first NUM_ENVS threads of the grid (blocks 0..3 at BLOCK=256).
    if (write_mask_tail && blockIdx.x < (NUM_ENVS / BLOCK)) {
        const int e = blockIdx.x * BLOCK + threadIdx.x;
        const float s = __ldg(&similarities[e]);
        const int   m = __ldg(&mem_mask[e]);
        const int  nm = m + ((m != MEM_SIZE && s > NOVELTY_THRESHOLD) ? 1 : 0);
        out[MEM_ELEMS + (size_t)e] = (float)nm;
    }
}

extern "C" void kernel_launch(void* const* d_in, const int* in_sizes, int n_in,
                              void* d_out, int out_size)
{
    // Inputs per reference order:
    //   0: memory        float32 [E, M, D]
    //   1: obs_features  float32 [E, D]
    //   2: similarities  float32 [E]
    //   3: mem_mask      int32   [E]
    //   4: rand_idx      int32   [E]
    const float4* mem4         = (const float4*)d_in[0];
    const float4* obs4         = (const float4*)d_in[1];
    const float*  similarities = (const float*)d_in[2];
    const int*    mem_mask     = (const int*)d_in[3];
    const int*    rand_idx     = (const int*)d_in[4];
    float*        out          = (float*)d_out;

    const int write_mask_tail = ((size_t)out_size > MEM_ELEMS) ? 1 : 0;

    reachability_update_kernel<<<GRID, BLOCK>>>(
        mem4, obs4, similarities, mem_mask, rand_idx,
        (float4*)out, out, write_mask_tail);
}

// round 4
// speedup vs baseline: 1.0837x; 1.0023x over previous
#include <cuda_runtime.h>
#include <cuda_bf16.h>
#include <cstdint>

// Problem constants (reference: NUM_ENVS=1024, MEM_SIZE=200, FEAT=512)
#define NUM_ENVS 1024
#define MEM_SIZE 200
#define FEAT     512
#define NOVELTY_THRESHOLD 0.5f

#define MEM_ELEMS   ((size_t)NUM_ENVS * MEM_SIZE * FEAT)  // 104,857,600 floats
#define F4_PER_ROW  (FEAT / 4)                            // 128 float4 per row
#define F4_PER_ENV  (MEM_SIZE * F4_PER_ROW)               // 25,600 float4 per env
#define BLOCK       128
#define UNROLL      8
#define SEGS        (F4_PER_ENV / (BLOCK * UNROLL))       // 25 segments per env

// Env-aligned fused copy + conditional row replacement.
// grid = (SEGS, NUM_ENVS). Each block covers rows [seg*8, seg*8+8) of env
// blockIdx.y; thread t handles column t of each of those 8 rows. Per-env
// scalars load once; 8 independent LDG.128s are front-batched (MLP=8).
__global__ void __launch_bounds__(BLOCK)
reachability_update_kernel(
    const float4* __restrict__ mem4,          // [E*M*128]
    const float4* __restrict__ obs4,          // [E*128]
    const float*  __restrict__ similarities,  // [E]
    const int*    __restrict__ mem_mask,      // [E]
    const int*    __restrict__ rand_idx,      // [E]
    float4*       __restrict__ out4,
    float*        __restrict__ out,           // scalar view (mask tail)
    int write_mask_tail)
{
    const int e   = blockIdx.y;
    const int seg = blockIdx.x;
    const int tid = threadIdx.x;

    // Per-env scalars: once per thread, warp-uniform broadcast loads.
    const float s    = __ldg(&similarities[e]);
    const int   m    = __ldg(&mem_mask[e]);
    const bool  add  = (s > NOVELTY_THRESHOLD);
    const bool  full = (m == MEM_SIZE);
    const int   nm   = m + ((!full && add) ? 1 : 0);

    int target = -1;  // row within env that gets replaced (-1 = none)
    if (add) target = full ? __ldg(&rand_idx[e]) : (nm - 1);

    if (write_mask_tail && seg == 0 && tid == 0) {
        out[MEM_ELEMS + (size_t)e] = (float)nm;
    }

    const size_t env_base = (size_t)e * F4_PER_ENV;
    const int    row0     = seg * UNROLL;            // first row of this block
    const size_t base     = env_base + (size_t)row0 * F4_PER_ROW + tid;

    const float4 obs_v = __ldg(&obs4[(size_t)e * F4_PER_ROW + tid]);

    // Front-batched independent loads (MLP=8/thread).
    float4 v[UNROLL];
#pragma unroll
    for (int j = 0; j < UNROLL; j++)
        v[j] = __ldcs(&mem4[base + (size_t)j * F4_PER_ROW]);

    // Replace the target row's data if it falls in this block's 8 rows.
#pragma unroll
    for (int j = 0; j < UNROLL; j++)
        if (row0 + j == target) v[j] = obs_v;

    // Streaming stores.
#pragma unroll
    for (int j = 0; j < UNROLL; j++)
        __stcs(&out4[base + (size_t)j * F4_PER_ROW], v[j]);
}

extern "C" void kernel_launch(void* const* d_in, const int* in_sizes, int n_in,
                              void* d_out, int out_size)
{
    // Inputs per reference order:
    //   0: memory        float32 [E, M, D]
    //   1: obs_features  float32 [E, D]
    //   2: similarities  float32 [E]
    //   3: mem_mask      int32   [E]
    //   4: rand_idx      int32   [E]
    const float4* mem4         = (const float4*)d_in[0];
    const float4* obs4         = (const float4*)d_in[1];
    const float*  similarities = (const float*)d_in[2];
    const int*    mem_mask     = (const int*)d_in[3];
    const int*    rand_idx     = (const int*)d_in[4];
    float*        out          = (float*)d_out;

    const int write_mask_tail = ((size_t)out_size > MEM_ELEMS) ? 1 : 0;

    dim3 grid(SEGS, NUM_ENVS);
    reachability_update_kernel<<<grid, BLOCK>>>(
        mem4, obs4, similarities, mem_mask, rand_idx,
        (float4*)out, out, write_mask_tail);
}